// round 11
// baseline (speedup 1.0000x reference)
#include <cuda_runtime.h>
#include <cstdint>

#define N_TOTAL   4096
#define NN_NODES  1024
#define NN_MARB   3072
#define NN_EATERS 64
#define EPS_F     1e-6f
#define NWARPS    16
#define NBLOCKS   128

__device__ __forceinline__ float rsqrt_fast(float x) {
    float r;
    asm("rsqrt.approx.f32 %0, %1;" : "=f"(r) : "f"(x));
    return r;
}

__device__ int g_ticket = 0;   // last-block election; reset by the winner

// 128 blocks x 512 threads (16 warps). Block b owns bodies [b*32, b*32+32)
// (one per lane, replicated across all 16 warps). Each warp accumulates a
// disjoint 128-body j-slice per tile; 2 tiles of 2048 float4 (x,y,m,0).
// Scalar math: 9 fma-pipe ops + 1 MUFU + 1 LDS.128 per pair.
// After integration, the LAST block (ticket 127) computes eaten for all
// marbles — it never waits on anyone (it is last by definition).
__global__ __launch_bounds__(512, 1)
void nbody_fused_kernel(const float* __restrict__ pos,
                        const float* __restrict__ vel,
                        const float* __restrict__ mass,
                        const int*   __restrict__ eidx,
                        const float* __restrict__ erad,
                        const float* __restrict__ dtp,
                        float* __restrict__ out) {
    __shared__ float4 sh[2048];                 // (x, y, m, 0)   32 KB
    __shared__ float2 spart[NWARPS][32];
    __shared__ float  s_ex[NN_EATERS], s_ey[NN_EATERS], s_er2[NN_EATERS];
    __shared__ int    s_last;

    const int tid  = threadIdx.x;
    const int lane = tid & 31;
    const int warp = tid >> 5;
    const int i    = blockIdx.x * 32 + lane;

    const float2 p = ((const float2*)pos)[i];
    const float px = p.x, py = p.y;

    float ax = 0.0f, ay = 0.0f;

    #pragma unroll
    for (int tile = 0; tile < 2; tile++) {
        // Cooperative fill: 2048 bodies, 4 per thread.
        #pragma unroll
        for (int k = 0; k < 4; k++) {
            const int j  = k * 512 + tid;
            const int gj = tile * 2048 + j;
            float2 q = ((const float2*)pos)[gj];
            sh[j] = make_float4(q.x, q.y, mass[gj], 0.0f);
        }
        __syncthreads();

        const int base = warp * 128;            // 128 bodies per warp
        #pragma unroll 8
        for (int jj = 0; jj < 128; jj++) {
            const float4 q = sh[base + jj];     // LDS.128, warp-uniform
            const float dx = q.x - px;
            const float dy = q.y - py;
            const float d2 = fmaf(dx, dx, fmaf(dy, dy, EPS_F));
            const float r  = rsqrt_fast(d2);    // MUFU.RSQ
            const float r2 = r * r;
            const float mr = r * q.z;
            const float w  = r2 * mr;           // m_j * (d2+eps)^-1.5
            // Coincident pair (incl. j==i): dx=dy=0 -> contributes 0,
            // matching the reference's masked inv_d3.
            ax = fmaf(w, dx, ax);
            ay = fmaf(w, dy, ay);
        }
        __syncthreads();
    }

    spart[warp][lane] = make_float2(ax, ay);
    __syncthreads();

    if (warp == 0) {
        float fx = 0.0f, fy = 0.0f;
        #pragma unroll
        for (int w = 0; w < NWARPS; w++) {
            fx += spart[w][lane].x;
            fy += spart[w][lane].y;
        }
        const float dt = dtp[0];
        const float vx = vel[2 * i]     + fx * dt;
        const float vy = vel[2 * i + 1] + fy * dt;
        const float nx = px + vx * dt;
        const float ny = py + vy * dt;
        // state_new = stack([pos_new, vel_new]) : pos block first, then vel.
        out[2 * i]                   = nx;
        out[2 * i + 1]               = ny;
        out[2 * N_TOTAL + 2 * i]     = vx;
        out[2 * N_TOTAL + 2 * i + 1] = vy;
    }

    // ---- Last-block election (no block ever waits on another) ----
    __syncthreads();                            // order warp0 stores before ticket
    if (tid == 0) {
        __threadfence();                        // publish this block's pos_new
        int t = atomicAdd(&g_ticket, 1);
        s_last = (t == NBLOCKS - 1);
    }
    __syncthreads();
    if (!s_last) return;

    // ---- Winner: all 128 blocks' pos_new are globally visible ----
    if (tid == 0) {
        g_ticket = 0;                           // reset for next graph replay
        __threadfence();                        // acquire prior blocks' stores
    }

    if (tid < NN_EATERS) {
        const int e = eidx[tid];                // node index (< 1024)
        const float2 ep = __ldcg((const float2*)out + e);
        s_ex[tid] = ep.x;
        s_ey[tid] = ep.y;
        const float r = erad[tid];
        s_er2[tid] = r * r;
    }
    __syncthreads();

    // 3072 marbles / 512 threads = 6 per thread.
    #pragma unroll
    for (int q = 0; q < NN_MARB / 512; q++) {
        const int m = q * 512 + tid;
        const float2 mp = __ldcg((const float2*)out + NN_NODES + m);
        int eaten = 0;
        #pragma unroll
        for (int k = 0; k < NN_EATERS; k++) {
            const float dx = mp.x - s_ex[k];
            const float dy = mp.y - s_ey[k];
            const float d2 = fmaf(dx, dx, dy * dy);
            eaten |= (d2 <= s_er2[k]);
        }
        out[4 * N_TOTAL + m] = eaten ? 1.0f : 0.0f;
    }
}

extern "C" void kernel_launch(void* const* d_in, const int* in_sizes, int n_in,
                              void* d_out, int out_size) {
    const float* positions  = (const float*)d_in[0];
    const float* velocities = (const float*)d_in[1];
    const float* masses     = (const float*)d_in[2];
    const int*   eater_idx  = (const int*)  d_in[3];
    const float* eater_rad  = (const float*)d_in[4];
    const float* dt         = (const float*)d_in[5];
    float* out = (float*)d_out;

    nbody_fused_kernel<<<NBLOCKS, 512>>>(positions, velocities, masses,
                                         eater_idx, eater_rad, dt, out);
}

// round 12
// speedup vs baseline: 1.3661x; 1.3661x over previous
#include <cuda_runtime.h>
#include <cstdint>

#define N_TOTAL   4096
#define NN_NODES  1024
#define NN_MARB   3072
#define NN_EATERS 64
#define EPS_F     1e-6f
#define NTHREADS  256
#define NWARPS    8
#define NBLOCKS   128

__device__ __forceinline__ float rsqrt_fast(float x) {
    float r;
    asm("rsqrt.approx.f32 %0, %1;" : "=f"(r) : "f"(x));
    return r;
}

__device__ int g_ticket = 0;   // last-block election; reset by the winner

// 128 blocks x 256 threads (8 warps). Block b owns bodies [b*32, b*32+32)
// (one per lane, replicated across the 8 warps). Each warp accumulates a
// disjoint 256-body j-slice per tile; 2 tiles of 2048 float4 (x,y,m,0).
// Scalar math: 9 fma-pipe ops + 1 MUFU + 1 LDS.128 per pair.
// After integration every block takes a ticket; the one drawing the LAST
// ticket (which waits on nobody) computes eaten for all marbles.
// 256 threads => 255-reg budget: tail state cannot force spills in the loop.
__global__ __launch_bounds__(NTHREADS, 1)
void nbody_fused_kernel(const float* __restrict__ pos,
                        const float* __restrict__ vel,
                        const float* __restrict__ mass,
                        const int*   __restrict__ eidx,
                        const float* __restrict__ erad,
                        const float* __restrict__ dtp,
                        float* __restrict__ out) {
    __shared__ float4 sh[2048];                 // (x, y, m, 0)   32 KB
    __shared__ float2 spart[NWARPS][32];
    __shared__ float  s_ex[NN_EATERS], s_ey[NN_EATERS], s_er2[NN_EATERS];
    __shared__ int    s_last;

    const int tid  = threadIdx.x;
    const int lane = tid & 31;
    const int warp = tid >> 5;
    const int i    = blockIdx.x * 32 + lane;

    const float2 p = ((const float2*)pos)[i];
    const float px = p.x, py = p.y;

    float ax = 0.0f, ay = 0.0f;

    #pragma unroll
    for (int tile = 0; tile < 2; tile++) {
        // Cooperative fill: 2048 bodies, 8 per thread.
        #pragma unroll
        for (int k = 0; k < 8; k++) {
            const int j  = k * NTHREADS + tid;
            const int gj = tile * 2048 + j;
            float2 q = ((const float2*)pos)[gj];
            sh[j] = make_float4(q.x, q.y, mass[gj], 0.0f);
        }
        __syncthreads();

        const int base = warp * 256;            // 256 bodies per warp
        #pragma unroll 8
        for (int jj = 0; jj < 256; jj++) {
            const float4 q = sh[base + jj];     // LDS.128, warp-uniform
            const float dx = q.x - px;
            const float dy = q.y - py;
            const float d2 = fmaf(dx, dx, fmaf(dy, dy, EPS_F));
            const float r  = rsqrt_fast(d2);    // MUFU.RSQ
            const float r2 = r * r;
            const float mr = r * q.z;
            const float w  = r2 * mr;           // m_j * (d2+eps)^-1.5
            // Coincident pair (incl. j==i): dx=dy=0 -> contributes 0,
            // matching the reference's masked inv_d3.
            ax = fmaf(w, dx, ax);
            ay = fmaf(w, dy, ay);
        }
        __syncthreads();
    }

    spart[warp][lane] = make_float2(ax, ay);
    __syncthreads();

    if (warp == 0) {
        float fx = 0.0f, fy = 0.0f;
        #pragma unroll
        for (int w = 0; w < NWARPS; w++) {
            fx += spart[w][lane].x;
            fy += spart[w][lane].y;
        }
        const float dt = dtp[0];
        const float vx = vel[2 * i]     + fx * dt;
        const float vy = vel[2 * i + 1] + fy * dt;
        const float nx = px + vx * dt;
        const float ny = py + vy * dt;
        // state_new = stack([pos_new, vel_new]) : pos block first, then vel.
        out[2 * i]                   = nx;
        out[2 * i + 1]               = ny;
        out[2 * N_TOTAL + 2 * i]     = vx;
        out[2 * N_TOTAL + 2 * i + 1] = vy;
    }

    // ---- Last-block election (no block ever waits on another) ----
    __syncthreads();                            // order warp0 stores before ticket
    if (tid == 0) {
        __threadfence();                        // publish this block's pos_new
        int t = atomicAdd(&g_ticket, 1);
        s_last = (t == NBLOCKS - 1);
    }
    __syncthreads();
    if (!s_last) return;

    // ---- Winner: all 128 blocks' pos_new are globally visible ----
    if (tid == 0) {
        g_ticket = 0;                           // reset for next graph replay
        __threadfence();                        // acquire prior blocks' stores
    }

    if (tid < NN_EATERS) {
        const int e = eidx[tid];                // node index (< 1024)
        const float2 ep = __ldcg((const float2*)out + e);
        s_ex[tid] = ep.x;
        s_ey[tid] = ep.y;
        const float r = erad[tid];
        s_er2[tid] = r * r;
    }
    __syncthreads();

    // 3072 marbles / 256 threads = 12 per thread.
    #pragma unroll
    for (int q = 0; q < NN_MARB / NTHREADS; q++) {
        const int m = q * NTHREADS + tid;
        const float2 mp = __ldcg((const float2*)out + NN_NODES + m);
        int eaten = 0;
        #pragma unroll
        for (int k = 0; k < NN_EATERS; k++) {
            const float dx = mp.x - s_ex[k];
            const float dy = mp.y - s_ey[k];
            const float d2 = fmaf(dx, dx, dy * dy);
            eaten |= (d2 <= s_er2[k]);
        }
        out[4 * N_TOTAL + m] = eaten ? 1.0f : 0.0f;
    }
}

extern "C" void kernel_launch(void* const* d_in, const int* in_sizes, int n_in,
                              void* d_out, int out_size) {
    const float* positions  = (const float*)d_in[0];
    const float* velocities = (const float*)d_in[1];
    const float* masses     = (const float*)d_in[2];
    const int*   eater_idx  = (const int*)  d_in[3];
    const float* eater_rad  = (const float*)d_in[4];
    const float* dt         = (const float*)d_in[5];
    float* out = (float*)d_out;

    nbody_fused_kernel<<<NBLOCKS, NTHREADS>>>(positions, velocities, masses,
                                              eater_idx, eater_rad, dt, out);
}

// round 13
// speedup vs baseline: 2.2038x; 1.6132x over previous
#include <cuda_runtime.h>
#include <cstdint>

#define N_TOTAL   4096
#define NN_NODES  1024
#define NN_MARB   3072
#define NN_EATERS 64
#define EPS_F     1e-6f
#define NTHREADS  256
#define NWARPS    8

__device__ __forceinline__ float rsqrt_fast(float x) {
    float r;
    asm("rsqrt.approx.f32 %0, %1;" : "=f"(r) : "f"(x));
    return r;
}

// 128 blocks x 256 threads (8 warps). Block b owns bodies [b*32, b*32+32)
// (one per lane, replicated across the 8 warps). Each warp accumulates a
// disjoint 512-body j-slice via 2 shared tiles of 2048 float4 (x,y,m,0).
// Scalar math: 9 fma-pipe ops + 1 MUFU + 1 LDS.128 per pair.
__global__ __launch_bounds__(NTHREADS, 1)
void nbody_kernel(const float* __restrict__ pos,
                  const float* __restrict__ vel,
                  const float* __restrict__ mass,
                  const float* __restrict__ dtp,
                  float* __restrict__ out) {
    __shared__ float4 sh[2048];                 // (x, y, m, 0)   32 KB
    __shared__ float2 spart[NWARPS][32];

    const int tid  = threadIdx.x;
    const int lane = tid & 31;
    const int warp = tid >> 5;
    const int i    = blockIdx.x * 32 + lane;

    const float2 p = ((const float2*)pos)[i];
    const float px = p.x, py = p.y;

    float ax = 0.0f, ay = 0.0f;

    #pragma unroll
    for (int tile = 0; tile < 2; tile++) {
        // Cooperative fill: 2048 bodies, 8 per thread, straight from global.
        #pragma unroll
        for (int k = 0; k < 8; k++) {
            const int j  = k * NTHREADS + tid;
            const int gj = tile * 2048 + j;
            float2 q = ((const float2*)pos)[gj];
            sh[j] = make_float4(q.x, q.y, mass[gj], 0.0f);
        }
        __syncthreads();

        const int base = warp * 256;            // 256 bodies per warp
        #pragma unroll 8
        for (int jj = 0; jj < 256; jj++) {
            const float4 q = sh[base + jj];     // LDS.128, warp-uniform
            const float dx = q.x - px;
            const float dy = q.y - py;
            const float d2 = fmaf(dx, dx, fmaf(dy, dy, EPS_F));
            const float r  = rsqrt_fast(d2);    // MUFU.RSQ
            const float r2 = r * r;
            const float mr = r * q.z;
            const float w  = r2 * mr;           // m_j * (d2+eps)^-1.5
            // Coincident pair (incl. j==i): dx=dy=0 -> contributes 0,
            // matching the reference's masked inv_d3.
            ax = fmaf(w, dx, ax);
            ay = fmaf(w, dy, ay);
        }
        __syncthreads();
    }

    spart[warp][lane] = make_float2(ax, ay);
    __syncthreads();

    if (warp == 0) {
        float fx = 0.0f, fy = 0.0f;
        #pragma unroll
        for (int w = 0; w < NWARPS; w++) {
            fx += spart[w][lane].x;
            fy += spart[w][lane].y;
        }
        const float dt = dtp[0];
        const float vx = vel[2 * i]     + fx * dt;
        const float vy = vel[2 * i + 1] + fy * dt;
        const float nx = px + vx * dt;
        const float ny = py + vy * dt;
        // state_new = stack([pos_new, vel_new]) : pos block first, then vel.
        out[2 * i]                   = nx;
        out[2 * i + 1]               = ny;
        out[2 * N_TOTAL + 2 * i]     = vx;
        out[2 * N_TOTAL + 2 * i + 1] = vy;
    }
}

// 12 blocks x 256 threads: one thread per marble.
__global__ __launch_bounds__(NTHREADS, 1)
void eaten_kernel(const int* __restrict__ eidx,
                  const float* __restrict__ erad,
                  float* __restrict__ out) {
    __shared__ float ex[NN_EATERS], ey[NN_EATERS], er2[NN_EATERS];
    const int tid = threadIdx.x;
    if (tid < NN_EATERS) {
        int e = eidx[tid];                 // index into nodes (< 1024)
        float2 ep = *(const float2*)(out + 2 * e);
        ex[tid] = ep.x;
        ey[tid] = ep.y;
        float r = erad[tid];
        er2[tid] = r * r;
    }
    __syncthreads();

    const int m = blockIdx.x * blockDim.x + tid;   // marble 0..3071
    const float2 mp = ((const float2*)out)[NN_NODES + m];
    int eaten = 0;
    #pragma unroll
    for (int k = 0; k < NN_EATERS; k++) {
        float dx = mp.x - ex[k];
        float dy = mp.y - ey[k];
        float d2 = fmaf(dx, dx, dy * dy);
        eaten |= (d2 <= er2[k]);
    }
    out[4 * N_TOTAL + m] = eaten ? 1.0f : 0.0f;
}

extern "C" void kernel_launch(void* const* d_in, const int* in_sizes, int n_in,
                              void* d_out, int out_size) {
    const float* positions  = (const float*)d_in[0];
    const float* velocities = (const float*)d_in[1];
    const float* masses     = (const float*)d_in[2];
    const int*   eater_idx  = (const int*)  d_in[3];
    const float* eater_rad  = (const float*)d_in[4];
    const float* dt         = (const float*)d_in[5];
    float* out = (float*)d_out;

    nbody_kernel<<<N_TOTAL / 32, NTHREADS>>>(positions, velocities, masses, dt, out);
    eaten_kernel<<<NN_MARB / NTHREADS, NTHREADS>>>(eater_idx, eater_rad, out);
}